// round 2
// baseline (speedup 1.0000x reference)
#include <cuda_runtime.h>

#define S 26
#define D 7
#define DA 11
#define V 29

// Shared-parameter layout (floats)
#define P_EMB   0      // 203
#define P_POS   203    // 182
#define P_WK0   385
#define P_BK0   462
#define P_WQ0   473
#define P_BQ0   550
#define P_WV0   561
#define P_BV0   638
#define P_WF0   649
#define P_BF0   726
#define P_WK1   733
#define P_BK1   810
#define P_WQ1   821
#define P_BQ1   898
#define P_WV1   909
#define P_BV1   986
#define P_WF1   997
#define P_BF1   1074
#define P_WOUT  1081
#define P_BOUT  1284
#define P_TOTAL 1313

__device__ __forceinline__ void cp(float* __restrict__ dst,
                                   const float* __restrict__ src,
                                   int n, int t, int nt)
{
    for (int i = t; i < n; i += nt) dst[i] = src[i];
}

__global__ __launch_bounds__(256, 1)
void bes_transformer_kernel(
    const int*   __restrict__ x,
    const float* __restrict__ emb_table,
    const float* __restrict__ pos,
    const float* __restrict__ wk0, const float* __restrict__ bk0,
    const float* __restrict__ wq0, const float* __restrict__ bq0,
    const float* __restrict__ wv0, const float* __restrict__ bv0,
    const float* __restrict__ wf0, const float* __restrict__ bf0,
    const float* __restrict__ wk1, const float* __restrict__ bk1,
    const float* __restrict__ wq1, const float* __restrict__ bq1,
    const float* __restrict__ wv1, const float* __restrict__ bv1,
    const float* __restrict__ wf1, const float* __restrict__ bf1,
    const float* __restrict__ wout, const float* __restrict__ bout,
    float* __restrict__ out)
{
    __shared__ float P[P_TOTAL];
    __shared__ int   xs[S];
    __shared__ float h[S][D];
    __shared__ float k[S][DA];
    __shared__ float q[S][DA];
    __shared__ float v[S][DA];
    __shared__ float att[S][S];
    __shared__ float res[S][DA];

    const int t  = threadIdx.x;
    const int nt = blockDim.x;

    // ---- single batched load phase: everything into shared memory ----
    // All loads issued back-to-back per thread -> one latency exposure.
    if (t < S) xs[t] = x[t];
    cp(P + P_EMB,  emb_table, V * D,  t, nt);
    cp(P + P_POS,  pos,       S * D,  t, nt);
    cp(P + P_WK0,  wk0, DA * D, t, nt);  cp(P + P_BK0, bk0, DA, t, nt);
    cp(P + P_WQ0,  wq0, DA * D, t, nt);  cp(P + P_BQ0, bq0, DA, t, nt);
    cp(P + P_WV0,  wv0, DA * D, t, nt);  cp(P + P_BV0, bv0, DA, t, nt);
    cp(P + P_WF0,  wf0, D * DA, t, nt);  cp(P + P_BF0, bf0, D,  t, nt);
    cp(P + P_WK1,  wk1, DA * D, t, nt);  cp(P + P_BK1, bk1, DA, t, nt);
    cp(P + P_WQ1,  wq1, DA * D, t, nt);  cp(P + P_BQ1, bq1, DA, t, nt);
    cp(P + P_WV1,  wv1, DA * D, t, nt);  cp(P + P_BV1, bv1, DA, t, nt);
    cp(P + P_WF1,  wf1, D * DA, t, nt);  cp(P + P_BF1, bf1, D,  t, nt);
    cp(P + P_WOUT, wout, V * D, t, nt);  cp(P + P_BOUT, bout, V, t, nt);
    __syncthreads();

    // ---- embedding + positional ----
    for (int i = t; i < S * D; i += nt) {
        int s = i / D, d = i % D;
        h[s][d] = P[P_EMB + xs[s] * D + d] + P[P_POS + i];
    }
    __syncthreads();

    #pragma unroll 1
    for (int layer = 0; layer < 2; layer++) {
        const float* wk = P + (layer ? P_WK1 : P_WK0);
        const float* bk = P + (layer ? P_BK1 : P_BK0);
        const float* wq = P + (layer ? P_WQ1 : P_WQ0);
        const float* bq = P + (layer ? P_BQ1 : P_BQ0);
        const float* wv = P + (layer ? P_WV1 : P_WV0);
        const float* bv = P + (layer ? P_BV1 : P_BV0);
        const float* wf = P + (layer ? P_WF1 : P_WF0);
        const float* bf = P + (layer ? P_BF1 : P_BF0);

        // ---- K, Q, V projections: [S, DA] ----
        for (int i = t; i < S * DA; i += nt) {
            int s = i / DA, a = i % DA;
            float sk = bk[a], sq = bq[a], sv = bv[a];
            #pragma unroll
            for (int d = 0; d < D; d++) {
                float hv = h[s][d];
                sk += hv * wk[a * D + d];
                sq += hv * wq[a * D + d];
                sv += hv * wv[a * D + d];
            }
            k[s][a] = sk; q[s][a] = sq; v[s][a] = sv;
        }
        __syncthreads();

        // ---- attention scores (causal lower triangle only) ----
        for (int i = t; i < S * S; i += nt) {
            int r = i / S, c = i % S;
            if (c <= r) {
                float sum = 0.f;
                #pragma unroll
                for (int a = 0; a < DA; a++) sum += q[r][a] * k[c][a];
                att[r][c] = sum;
            }
        }
        __syncthreads();

        // ---- causal softmax: one thread per row, fast exp ----
        if (t < S) {
            float m = att[t][0];
            for (int c = 1; c <= t; c++) m = fmaxf(m, att[t][c]);
            float sum = 0.f;
            for (int c = 0; c <= t; c++) {
                float e = __expf(att[t][c] - m);
                att[t][c] = e;
                sum += e;
            }
            float inv = 1.f / sum;
            for (int c = 0; c <= t; c++) att[t][c] *= inv;
            for (int c = t + 1; c < S; c++) att[t][c] = 0.f;
        }
        __syncthreads();

        // ---- res = att @ v : [S, DA] ----
        for (int i = t; i < S * DA; i += nt) {
            int s = i / DA, a = i % DA;
            float r = 0.f;
            for (int c = 0; c <= s; c++) r += att[s][c] * v[c][a];
            res[s][a] = r;
        }
        __syncthreads();

        // ---- h = res @ wf^T + bf : [S, D] ----
        for (int i = t; i < S * D; i += nt) {
            int s = i / D, d = i % D;
            float r = bf[d];
            #pragma unroll
            for (int a = 0; a < DA; a++) r += res[s][a] * wf[d * DA + a];
            h[s][d] = r;
        }
        __syncthreads();

        // ---- second-layer attention matrix goes to output ----
        if (layer == 1) {
            for (int i = t; i < S * S; i += nt)
                out[S * V + i] = att[i / S][i % S];
        }
    }

    // ---- logits: out = h @ wout^T + bout : [S, V] ----
    for (int i = t; i < S * V; i += nt) {
        int s = i / V, vv = i % V;
        float r = P[P_BOUT + vv];
        #pragma unroll
        for (int d = 0; d < D; d++) r += h[s][d] * P[P_WOUT + vv * D + d];
        out[s * V + vv] = r;
    }
}

extern "C" void kernel_launch(void* const* d_in, const int* in_sizes, int n_in,
                              void* d_out, int out_size)
{
    bes_transformer_kernel<<<1, 256>>>(
        (const int*)  d_in[0],   // x
        (const float*)d_in[1],   // emb_table
        (const float*)d_in[2],   // pos
        (const float*)d_in[3],  (const float*)d_in[4],   // w_k0, b_k0
        (const float*)d_in[5],  (const float*)d_in[6],   // w_q0, b_q0
        (const float*)d_in[7],  (const float*)d_in[8],   // w_v0, b_v0
        (const float*)d_in[9],  (const float*)d_in[10],  // w_f0, b_f0
        (const float*)d_in[11], (const float*)d_in[12],  // w_k1, b_k1
        (const float*)d_in[13], (const float*)d_in[14],  // w_q1, b_q1
        (const float*)d_in[15], (const float*)d_in[16],  // w_v1, b_v1
        (const float*)d_in[17], (const float*)d_in[18],  // w_f1, b_f1
        (const float*)d_in[19], (const float*)d_in[20],  // w_out, b_out
        (float*)d_out);
}

// round 3
// speedup vs baseline: 1.9476x; 1.9476x over previous
#include <cuda_runtime.h>

#define S 26
#define D 7
#define DA 11
#define V 29
#define NT 384

__global__ __launch_bounds__(NT, 1)
void bes_transformer_kernel(
    const int*   __restrict__ x,
    const float* __restrict__ emb_table,
    const float* __restrict__ pos,
    const float* __restrict__ wk0, const float* __restrict__ bk0,
    const float* __restrict__ wq0, const float* __restrict__ bq0,
    const float* __restrict__ wv0, const float* __restrict__ bv0,
    const float* __restrict__ wf0, const float* __restrict__ bf0,
    const float* __restrict__ wk1, const float* __restrict__ bk1,
    const float* __restrict__ wq1, const float* __restrict__ bq1,
    const float* __restrict__ wv1, const float* __restrict__ bv1,
    const float* __restrict__ wf1, const float* __restrict__ bf1,
    const float* __restrict__ wout, const float* __restrict__ bout,
    float* __restrict__ out)
{
    __shared__ float h[S][D];
    __shared__ float k[S][DA];
    __shared__ float q[S][DA];
    __shared__ float v[S][DA];
    __shared__ float att[S][S];   // holds exp(q.k) for c<=r; upper tri untouched
    __shared__ float res[S][DA];
    __shared__ float inv[S];      // 1 / row-sum of exp

    const int t = threadIdx.x;

    // ---- embedding + positional (182 elems, single shot) ----
    if (t < S * D) {
        int s = t / D, d = t % D;
        h[s][d] = emb_table[x[s] * D + d] + pos[t];
    }
    __syncthreads();

    #pragma unroll 1
    for (int layer = 0; layer < 2; layer++) {
        const float* wk = layer ? wk1 : wk0;
        const float* bk = layer ? bk1 : bk0;
        const float* wq = layer ? wq1 : wq0;
        const float* bq = layer ? bq1 : bq0;
        const float* wv = layer ? wv1 : wv0;
        const float* bv = layer ? bv1 : bv0;
        const float* wf = layer ? wf1 : wf0;
        const float* bf = layer ? bf1 : bf0;

        // ---- K, Q, V projections (286 elems, single shot) ----
        if (t < S * DA) {
            int s = t / DA, a = t % DA;
            float sk = bk[a], sq = bq[a], sv = bv[a];
            #pragma unroll
            for (int d = 0; d < D; d++) {
                float hv = h[s][d];
                sk += hv * wk[a * D + d];
                sq += hv * wq[a * D + d];
                sv += hv * wv[a * D + d];
            }
            k[s][a] = sk; q[s][a] = sq; v[s][a] = sv;
        }
        __syncthreads();

        // ---- fused scores + exp (no max-subtraction; values are small) ----
        #pragma unroll
        for (int i = t; i < S * S; i += NT) {
            int r = i / S, c = i % S;
            if (c <= r) {
                float sum = 0.f;
                #pragma unroll
                for (int a = 0; a < DA; a++) sum += q[r][a] * k[c][a];
                att[r][c] = __expf(sum);
            }
        }
        __syncthreads();

        // ---- fused row-sum + AV + normalize: res = softmax(att) @ v ----
        if (t < S * DA) {
            int s = t / DA, a = t % DA;
            float sum = 0.f, dot = 0.f;
            for (int c = 0; c <= s; c++) {
                float e = att[s][c];
                sum += e;
                dot += e * v[c][a];
            }
            float iv = __frcp_rn(sum);
            res[s][a] = dot * iv;
            if (a == 0) inv[s] = iv;
        }
        __syncthreads();

        // ---- h = res @ wf^T + bf, and (layer 1) emit normalized att ----
        if (t < S * D) {
            int s = t / D, d = t % D;
            float r = bf[d];
            #pragma unroll
            for (int a = 0; a < DA; a++) r += res[s][a] * wf[d * DA + a];
            h[s][d] = r;
        }
        if (layer == 1) {
            #pragma unroll
            for (int i = t; i < S * S; i += NT) {
                int r = i / S, c = i % S;
                out[S * V + i] = (c <= r) ? att[r][c] * inv[r] : 0.f;
            }
        }
        __syncthreads();
    }

    // ---- logits: out = h @ wout^T + bout (754 elems, 2 shots) ----
    #pragma unroll
    for (int i = t; i < S * V; i += NT) {
        int s = i / V, vv = i % V;
        float r = bout[vv];
        #pragma unroll
        for (int d = 0; d < D; d++) r += h[s][d] * wout[vv * D + d];
        out[i] = r;
    }
}

extern "C" void kernel_launch(void* const* d_in, const int* in_sizes, int n_in,
                              void* d_out, int out_size)
{
    bes_transformer_kernel<<<1, NT>>>(
        (const int*)  d_in[0],   // x
        (const float*)d_in[1],   // emb_table
        (const float*)d_in[2],   // pos
        (const float*)d_in[3],  (const float*)d_in[4],   // w_k0, b_k0
        (const float*)d_in[5],  (const float*)d_in[6],   // w_q0, b_q0
        (const float*)d_in[7],  (const float*)d_in[8],   // w_v0, b_v0
        (const float*)d_in[9],  (const float*)d_in[10],  // w_f0, b_f0
        (const float*)d_in[11], (const float*)d_in[12],  // w_k1, b_k1
        (const float*)d_in[13], (const float*)d_in[14],  // w_q1, b_q1
        (const float*)d_in[15], (const float*)d_in[16],  // w_v1, b_v1
        (const float*)d_in[17], (const float*)d_in[18],  // w_f1, b_f1
        (const float*)d_in[19], (const float*)d_in[20],  // w_out, b_out
        (float*)d_out);
}